// round 13
// baseline (speedup 1.0000x reference)
#include <cuda_runtime.h>
#include <cuda_fp16.h>
#include <math.h>
#include <stdint.h>

#define B_ 8
#define N_ 2048
#define D_ 256

// ---------------------------------------------------------------------------
// helpers (baseline PTX only: cp.async / ldmatrix / mma.sync — compute_100 OK)
// ---------------------------------------------------------------------------
__device__ __forceinline__ unsigned smem_u32(const void* p) {
    unsigned a;
    asm("{ .reg .u64 t; cvta.to.shared.u64 t, %1; cvt.u32.u64 %0, t; }"
        : "=r"(a) : "l"(p));
    return a;
}
__device__ __forceinline__ int SWZ(int x) { return x ^ ((x >> 3) & 0x70); }

#define CP16(dst, src) \
    asm volatile("cp.async.cg.shared.global [%0], [%1], 16;" \
                 :: "r"((unsigned)(dst)), "l"(__cvta_generic_to_global(src)) : "memory")
#define CPC() asm volatile("cp.async.commit_group;" ::: "memory")
#define CPW0() asm volatile("cp.async.wait_group 0;" ::: "memory")
#define CPW1() asm volatile("cp.async.wait_group 1;" ::: "memory")

#define LDSM4(r0, r1, r2, r3, a) \
    asm volatile("ldmatrix.sync.aligned.m8n8.x4.shared.b16 {%0,%1,%2,%3}, [%4];" \
                 : "=r"(r0), "=r"(r1), "=r"(r2), "=r"(r3) : "r"((unsigned)(a)))

#define MMA(d, a0, a1, a2, a3, b0, b1) \
    asm volatile("mma.sync.aligned.m16n8k16.row.col.f32.f16.f16.f32 " \
                 "{%0,%1,%2,%3}, {%4,%5,%6,%7}, {%8,%9}, {%0,%1,%2,%3};" \
                 : "+f"((d)[0]), "+f"((d)[1]), "+f"((d)[2]), "+f"((d)[3]) \
                 : "r"(a0), "r"(a1), "r"(a2), "r"(a3), "r"(b0), "r"(b1))

// ---------------------------------------------------------------------------
// device globals (no allocation allowed)
// ---------------------------------------------------------------------------
__device__ float g_wl[D_];
__device__ float g_wr[D_];
__device__ __align__(16) float2 g_Elp[B_ * N_];   // (exp(hl), exp(0.2 hl))
__device__ __align__(16) float2 g_Erp[B_ * N_];   // (exp(hr), exp(0.2 hr))
__device__ __align__(16) __half g_Whf[D_ * D_];            // W fp16 row-major [o][k]
__device__ __align__(16) __half g_xh [B_ * N_ * D_];       // x fp16 row-major [m][k]
__device__ __align__(128) unsigned char g_ht[B_ * 32 * 32768]; // h^T fp16: [b][jt][d 256][j 64] swizzled

// ---------------- k_prep: block 0 -> wl/wr; blocks 1-16 -> W fp16 -----------
__global__ void k_prep(const float* __restrict__ W, const float* __restrict__ a)
{
    int t = threadIdx.x;                          // 1024 threads
    if (blockIdx.x == 0) {
        __shared__ float red[2][4][256];
        int d = t & 255, part = t >> 8;           // 4 o-partitions
        float sl = 0.f, sr = 0.f;
        int o0 = part * 64;
        #pragma unroll 8
        for (int o = o0; o < o0 + 64; ++o) {
            float w = W[o * D_ + d];
            sl = fmaf(a[o],      w, sl);
            sr = fmaf(a[D_ + o], w, sr);
        }
        red[0][part][d] = sl;
        red[1][part][d] = sr;
        __syncthreads();
        if (part == 0) {
            g_wl[d] = (red[0][0][d] + red[0][1][d]) + (red[0][2][d] + red[0][3][d]);
            g_wr[d] = (red[1][0][d] + red[1][1][d]) + (red[1][2][d] + red[1][3][d]);
        }
    } else {
        int i = (blockIdx.x - 1) * 1024 + t;      // one float4 each (16384 total)
        float4 v = ((const float4*)W)[i];
        __half2* o = (__half2*)g_Whf;
        o[i * 2]     = __floats2half2_rn(v.x, v.y);
        o[i * 2 + 1] = __floats2half2_rn(v.z, v.w);
    }
}

// ---------------- k_hlr: 2 rows/warp, hl/hr dots + exps + x->fp16 -----------
__global__ void k_hlr(const float* __restrict__ x)
{
    int w    = threadIdx.x >> 5;
    int lane = threadIdx.x & 31;
    int m0   = blockIdx.x * 16 + w * 2;           // rows m0, m0+1
    const float4* xr0 = (const float4*)(x + (size_t)m0 * D_);
    const float4* xr1 = (const float4*)(x + (size_t)(m0 + 1) * D_);
    const float4* wl4 = (const float4*)g_wl;
    const float4* wr4 = (const float4*)g_wr;

    float4 a0 = xr0[lane], a1 = xr0[lane + 32];   // 4 independent loads
    float4 b0 = xr1[lane], b1 = xr1[lane + 32];
    float4 l0 = wl4[lane], l1 = wl4[lane + 32];
    float4 r0 = wr4[lane], r1 = wr4[lane + 32];

    __half2* xo0 = (__half2*)(g_xh + (size_t)m0 * D_);
    __half2* xo1 = (__half2*)(g_xh + (size_t)(m0 + 1) * D_);
    xo0[lane * 2]            = __floats2half2_rn(a0.x, a0.y);
    xo0[lane * 2 + 1]        = __floats2half2_rn(a0.z, a0.w);
    xo0[(lane + 32) * 2]     = __floats2half2_rn(a1.x, a1.y);
    xo0[(lane + 32) * 2 + 1] = __floats2half2_rn(a1.z, a1.w);
    xo1[lane * 2]            = __floats2half2_rn(b0.x, b0.y);
    xo1[lane * 2 + 1]        = __floats2half2_rn(b0.z, b0.w);
    xo1[(lane + 32) * 2]     = __floats2half2_rn(b1.x, b1.y);
    xo1[(lane + 32) * 2 + 1] = __floats2half2_rn(b1.z, b1.w);

    float sl0 = a0.x * l0.x + a0.y * l0.y + a0.z * l0.z + a0.w * l0.w
              + a1.x * l1.x + a1.y * l1.y + a1.z * l1.z + a1.w * l1.w;
    float sr0 = a0.x * r0.x + a0.y * r0.y + a0.z * r0.z + a0.w * r0.w
              + a1.x * r1.x + a1.y * r1.y + a1.z * r1.z + a1.w * r1.w;
    float sl1 = b0.x * l0.x + b0.y * l0.y + b0.z * l0.z + b0.w * l0.w
              + b1.x * l1.x + b1.y * l1.y + b1.z * l1.z + b1.w * l1.w;
    float sr1 = b0.x * r0.x + b0.y * r0.y + b0.z * r0.z + b0.w * r0.w
              + b1.x * r1.x + b1.y * r1.y + b1.z * r1.z + b1.w * r1.w;

    #pragma unroll
    for (int off = 16; off > 0; off >>= 1) {
        sl0 += __shfl_xor_sync(0xFFFFFFFFu, sl0, off);
        sr0 += __shfl_xor_sync(0xFFFFFFFFu, sr0, off);
        sl1 += __shfl_xor_sync(0xFFFFFFFFu, sl1, off);
        sr1 += __shfl_xor_sync(0xFFFFFFFFu, sr1, off);
    }
    if (lane == 0) {
        g_Elp[m0]     = make_float2(expf(sl0), expf(0.2f * sl0));
        g_Erp[m0]     = make_float2(expf(sr0), expf(0.2f * sr0));
        g_Elp[m0 + 1] = make_float2(expf(sl1), expf(0.2f * sl1));
        g_Erp[m0 + 1] = make_float2(expf(sr1), expf(0.2f * sr1));
    }
}

// ---------------------------------------------------------------------------
// k_xh: h^T[d][j] = sum_k W[d][k] x[j][k]  (HMMA), smem-staged coalesced out
// CTA: 64 d x 256 j; warps m32 x n64; K loop 4 chunks of 64; 2 CTAs/SM
// ---------------------------------------------------------------------------
__global__ __launch_bounds__(256, 2) void k_xh()
{
    extern __shared__ char sm[];
    const int WS = 0, XS = 32768;
    unsigned sb = smem_u32(sm);
    int t = threadIdx.x, l = t & 31, w = t >> 5;
    int wm = w & 1, wn = w >> 1;
    int j0 = blockIdx.x * 256;
    int d0 = blockIdx.y * 64;

    #pragma unroll
    for (int q = 0; q < 8; ++q) {
        int idx = t + q * 256;
        int kc = idx >> 9, r = (idx >> 3) & 63, ch = idx & 7;
        CP16(sb + WS + kc * 8192 + SWZ(r * 128 + ch * 16),
             (const char*)g_Whf + (size_t)(d0 + r) * 512 + kc * 128 + ch * 16);
    }
    #pragma unroll
    for (int q = 0; q < 8; ++q) {
        int idx = t + q * 256, r = idx >> 3, ch = idx & 7;
        CP16(sb + XS + SWZ(r * 128 + ch * 16),
             (const char*)g_xh + (size_t)(j0 + r) * 512 + ch * 16);
    }
    CPC();

    float acc[8][2][4];
    #pragma unroll
    for (int i = 0; i < 8; ++i)
        #pragma unroll
        for (int m = 0; m < 2; ++m)
            #pragma unroll
            for (int c = 0; c < 4; ++c) acc[i][m][c] = 0.f;

    for (int kc = 0; kc < 4; ++kc) {
        if (kc < 3) {
            unsigned bbuf = sb + XS + ((kc + 1) & 1) * 32768;
            #pragma unroll
            for (int q = 0; q < 8; ++q) {
                int idx = t + q * 256, r = idx >> 3, ch = idx & 7;
                CP16(bbuf + SWZ(r * 128 + ch * 16),
                     (const char*)g_xh + (size_t)(j0 + r) * 512 + (kc + 1) * 128 + ch * 16);
            }
            CPC();
            CPW1();
        } else {
            CPW0();
        }
        __syncthreads();

        unsigned ab = sb + WS + kc * 8192;
        unsigned bb = sb + XS + (kc & 1) * 32768;
        #pragma unroll
        for (int ks = 0; ks < 4; ++ks) {
            unsigned a0[4], a1[4];
            LDSM4(a0[0], a0[1], a0[2], a0[3],
                  ab + SWZ((wm * 32      + (l & 15)) * 128 + ks * 32 + (l >> 4) * 16));
            LDSM4(a1[0], a1[1], a1[2], a1[3],
                  ab + SWZ((wm * 32 + 16 + (l & 15)) * 128 + ks * 32 + (l >> 4) * 16));
            #pragma unroll
            for (int nb2 = 0; nb2 < 4; ++nb2) {
                unsigned b0, b1, b2, b3;
                LDSM4(b0, b1, b2, b3,
                      bb + SWZ((wn * 64 + nb2 * 16 + (l & 15)) * 128 + ks * 32 + (l >> 4) * 16));
                MMA(acc[2*nb2][0],   a0[0], a0[1], a0[2], a0[3], b0, b2);
                MMA(acc[2*nb2][1],   a1[0], a1[1], a1[2], a1[3], b0, b2);
                MMA(acc[2*nb2+1][0], a0[0], a0[1], a0[2], a0[3], b1, b3);
                MMA(acc[2*nb2+1][1], a1[0], a1[1], a1[2], a1[3], b1, b3);
            }
        }
        __syncthreads();
    }

    // stage output (fp16, swizzled tile image) into smem, then coalesced copy
    #pragma unroll
    for (int mi = 0; mi < 2; ++mi) {
        int rd = wm * 32 + mi * 16 + (l >> 2);
        #pragma unroll
        for (int nb = 0; nb < 8; ++nb) {
            int jj = nb * 8 + 2 * (l & 3);
            __half2 v0 = __floats2half2_rn(acc[nb][mi][0], acc[nb][mi][1]);
            __half2 v1 = __floats2half2_rn(acc[nb][mi][2], acc[nb][mi][3]);
            *(__half2*)(sm + WS + wn * 8192 + SWZ( rd      * 128 + jj * 2)) = v0;
            *(__half2*)(sm + WS + wn * 8192 + SWZ((rd + 8) * 128 + jj * 2)) = v1;
        }
    }
    __syncthreads();

    int b   = j0 >> 11;
    int jt0 = (j0 & 2047) >> 6;
    #pragma unroll
    for (int q = 0; q < 8; ++q) {
        int c  = t + q * 256;                 // 2048 chunks x 16B
        int jt = c >> 9;
        int off = (c & 511) * 16;
        unsigned char* dst = g_ht + (size_t)(b * 32 + jt0 + jt) * 32768 + d0 * 128 + off;
        *(uint4*)dst = *(const uint4*)(sm + WS + c * 16);
    }
}

// ---------------------------------------------------------------------------
// k_aggr: fused masked-softmax aggregation (HMMA), ks-interleaved pipeline
// CTA 512 thr: i-tile M=128, warp tile m32 x n64 (wm, wn in 0..3), 32 j-tiles
// smem: H 3x32KB @0 | ADJ 2x32KB @98304 | P 2x16KB @163840 | ER 16KB @196608
//       | ELP 1KB @212992 | RSUM @214016   (total 214528)
// iter t: wait0 (G(t+1) landed) -> barrier -> per ks: {issue 1/4 of G(t+2);
//         P-quarter(t+1); LDSM+MMA chunk ks of t} -> commit
//   Fine-grained interleave keeps LSU/ALU/tensor pipes co-active instead of
//   lumped phases. ADJ copy/read is self-paired per thread (chunk t+512q).
// ---------------------------------------------------------------------------
__global__ __launch_bounds__(512) void k_aggr(const int* __restrict__ adj,
                                              float* __restrict__ out)
{
    extern __shared__ char sm[];
    const int HS = 0, AJ = 98304, PS = 163840, ERS = 196608;
    const int ELP = 212992, RSUM = 214016;
    unsigned sb = smem_u32(sm);
    int t = threadIdx.x, l = t & 31, w = t >> 5;
    int wm = w & 3, wn = w >> 2;
    int b = blockIdx.y, i0 = blockIdx.x * 128;
    float2* elp  = (float2*)(sm + ELP);
    float*  rsum = (float*)(sm + RSUM);

    const unsigned char* hsrc = g_ht + (size_t)b * 32 * 32768;
    const int*           adjb = adj + ((size_t)b * N_ + i0) * N_;

    // one quarter of P(nt): rep in 0..3, 4 values/thread
    #define P_CHUNK(nt, rep) do {                                                \
        char* pb = sm + PS + ((nt) & 1) * 16384;                                 \
        const int4*   aj4 = (const int4*)(sm + AJ + ((nt) & 1) * 32768);         \
        const float4* er4 = (const float4*)(sm + ERS);                           \
        int idx = t + (rep) * 512;                                               \
        int row = idx >> 4, c4 = idx & 15;                                       \
        int4 av = aj4[idx];                                                      \
        float2 el = elp[row];                                                    \
        float4 ea = er4[(nt) * 32 + c4 * 2];                                     \
        float4 eb = er4[(nt) * 32 + c4 * 2 + 1];                                 \
        float p0 = fmaxf(el.x * ea.x, el.y * ea.y);                              \
        float p1 = fmaxf(el.x * ea.z, el.y * ea.w);                              \
        float p2 = fmaxf(el.x * eb.x, el.y * eb.y);                              \
        float p3 = fmaxf(el.x * eb.z, el.y * eb.w);                              \
        p0 = av.x ? p0 : 0.f;  p1 = av.y ? p1 : 0.f;                             \
        p2 = av.z ? p2 : 0.f;  p3 = av.w ? p3 : 0.f;                             \
        __half2 h01 = __floats2half2_rn(p0, p1);                                 \
        __half2 h23 = __floats2half2_rn(p2, p3);                                 \
        uint2 pk;                                                                \
        pk.x = *(unsigned*)&h01;                                                 \
        pk.y = *(unsigned*)&h23;                                                 \
        *(uint2*)(pb + SWZ(row * 128 + c4 * 8)) = pk;                            \
    } while (0)

    // G0: H(0) + ADJ(0) + Er row + Elp
    #pragma unroll
    for (int q = 0; q < 4; ++q) {
        int idx = t + q * 512;
        CP16(sb + HS + idx * 16, hsrc + idx * 16);
    }
    #pragma unroll
    for (int q = 0; q < 4; ++q) {
        int idx = t + q * 512;
        CP16(sb + AJ + idx * 16, adjb + ((size_t)(idx >> 4)) * N_ + (idx & 15) * 4);
    }
    #pragma unroll
    for (int q = 0; q < 2; ++q) {
        int idx = t + q * 512;
        CP16(sb + ERS + idx * 16, (const char*)(g_Erp + b * N_) + idx * 16);
    }
    if (t < 64) CP16(sb + ELP + t * 16, (const char*)(g_Elp + b * N_ + i0) + t * 16);
    CPC();
    // G1: H(1) + ADJ(1)
    #pragma unroll
    for (int q = 0; q < 4; ++q) {
        int idx = t + q * 512;
        CP16(sb + HS + 32768 + idx * 16, hsrc + 32768 + idx * 16);
    }
    #pragma unroll
    for (int q = 0; q < 4; ++q) {
        int idx = t + q * 512;
        CP16(sb + AJ + 32768 + idx * 16,
             adjb + 64 + ((size_t)(idx >> 4)) * N_ + (idx & 15) * 4);
    }
    CPC();
    CPW1();                 // G0 arrived (G1 in flight)
    __syncthreads();

    #pragma unroll
    for (int rep = 0; rep < 4; ++rep) P_CHUNK(0, rep);

    float acc[8][2][4];
    #pragma unroll
    for (int i = 0; i < 8; ++i)
        #pragma unroll
        for (int m = 0; m < 2; ++m)
            #pragma unroll
            for (int c = 0; c < 4; ++c) acc[i][m][c] = 0.f;
    float sacc[2][4] = {{0.f,0.f,0.f,0.f},{0.f,0.f,0.f,0.f}};
    const unsigned ONESH = 0x3C003C00u;

    for (int tile = 0; tile < 32; ++tile) {
        CPW0();             // G(tile+1) fully landed (issued during iter-1)
        __syncthreads();    // H/P cross-thread visibility; buffer-reuse fence

        unsigned pbase = sb + PS + (tile & 1) * 16384;
        unsigned hbase = sb + HS + (tile % 3) * 32768;
        int nt2 = tile + 2;
        unsigned hdst = sb + HS + (nt2 % 3) * 32768;
        unsigned adst = sb + AJ + (nt2 & 1) * 32768;
        const unsigned char* hsr = hsrc + (size_t)nt2 * 32768;
        const int*           asr = adjb + nt2 * 64;

        #pragma unroll
        for (int ks = 0; ks < 4; ++ks) {
            if (tile < 30) {            // 1/4 of G(tile+2): 1 H + 1 ADJ chunk
                int idx = t + ks * 512;
                CP16(hdst + idx * 16, hsr + idx * 16);
                CP16(adst + idx * 16, asr + ((size_t)(idx >> 4)) * N_ + (idx & 15) * 4);
            }
            if (tile < 31) P_CHUNK(tile + 1, ks);

            unsigned a0[4], a1[4];
            LDSM4(a0[0], a0[1], a0[2], a0[3],
                  pbase + SWZ((wm * 32      + (l & 15)) * 128 + ks * 32 + (l >> 4) * 16));
            LDSM4(a1[0], a1[1], a1[2], a1[3],
                  pbase + SWZ((wm * 32 + 16 + (l & 15)) * 128 + ks * 32 + (l >> 4) * 16));
            if (wn == 0) {
                MMA(sacc[0], a0[0], a0[1], a0[2], a0[3], ONESH, ONESH);
                MMA(sacc[1], a1[0], a1[1], a1[2], a1[3], ONESH, ONESH);
            }
            #pragma unroll
            for (int nb2 = 0; nb2 < 4; ++nb2) {
                unsigned b0, b1, b2, b3;
                LDSM4(b0, b1, b2, b3,
                      hbase + SWZ((wn * 64 + nb2 * 16 + (l & 15)) * 128 + ks * 32 + (l >> 4) * 16));
                MMA(acc[2*nb2][0],   a0[0], a0[1], a0[2], a0[3], b0, b2);
                MMA(acc[2*nb2][1],   a1[0], a1[1], a1[2], a1[3], b0, b2);
                MMA(acc[2*nb2+1][0], a0[0], a0[1], a0[2], a0[3], b1, b3);
                MMA(acc[2*nb2+1][1], a1[0], a1[1], a1[2], a1[3], b1, b3);
            }
        }
        if (tile < 30) CPC();
    }

    __syncthreads();
    if (wn == 0 && (l & 3) == 0) {
        int r = wm * 32 + (l >> 2);
        rsum[r]      = sacc[0][0];
        rsum[r + 8]  = sacc[0][2];
        rsum[r + 16] = sacc[1][0];
        rsum[r + 24] = sacc[1][2];
    }
    __syncthreads();

    #pragma unroll
    for (int mi = 0; mi < 2; ++mi) {
        int r0 = wm * 32 + mi * 16 + (l >> 2);
        float s0 = rsum[r0], s1 = rsum[r0 + 8];
        float inv0 = (s0 > 0.f) ? 1.f / s0 : 0.f;
        float inv1 = (s1 > 0.f) ? 1.f / s1 : 0.f;
        float* o0 = out + ((size_t)b * N_ + i0 + r0) * D_;
        float* o1 = o0 + 8 * D_;
        #pragma unroll
        for (int nb = 0; nb < 8; ++nb) {
            int c = wn * 64 + nb * 8 + 2 * (l & 3);
            *(float2*)(o0 + c) = make_float2(acc[nb][mi][0] * inv0,
                                             acc[nb][mi][1] * inv0);
            *(float2*)(o1 + c) = make_float2(acc[nb][mi][2] * inv1,
                                             acc[nb][mi][3] * inv1);
        }
    }
}

// ---------------------------------------------------------------------------
extern "C" void kernel_launch(void* const* d_in, const int* in_sizes, int n_in,
                              void* d_out, int out_size)
{
    const float* x   = (const float*)d_in[0];   // (8,2048,256) f32
    const int*   adj = (const int*)  d_in[1];   // (8,2048,2048) i32
    const float* W   = (const float*)d_in[2];   // (256,256) f32
    const float* a   = (const float*)d_in[3];   // (1,512) f32
    float*       out = (float*)d_out;           // (8,2048,256) f32

    cudaFuncSetAttribute(k_xh,   cudaFuncAttributeMaxDynamicSharedMemorySize, 98304);
    cudaFuncSetAttribute(k_aggr, cudaFuncAttributeMaxDynamicSharedMemorySize, 214528);

    k_prep <<<17, 1024>>>(W, a);
    k_hlr  <<<(B_ * N_) / 16, 256>>>(x);
    k_xh   <<<dim3((B_ * N_) / 256, D_ / 64), 256, 98304>>>();
    k_aggr <<<dim3(N_ / 128, B_), 512, 214528>>>(adj, out);
}

// round 14
// speedup vs baseline: 1.1268x; 1.1268x over previous
#include <cuda_runtime.h>
#include <cuda_fp16.h>
#include <math.h>
#include <stdint.h>

#define B_ 8
#define N_ 2048
#define D_ 256

// ---------------------------------------------------------------------------
// helpers (baseline PTX only: cp.async / ldmatrix / mma.sync — compute_100 OK)
// ---------------------------------------------------------------------------
__device__ __forceinline__ unsigned smem_u32(const void* p) {
    unsigned a;
    asm("{ .reg .u64 t; cvta.to.shared.u64 t, %1; cvt.u32.u64 %0, t; }"
        : "=r"(a) : "l"(p));
    return a;
}
__device__ __forceinline__ int SWZ(int x) { return x ^ ((x >> 3) & 0x70); }

#define CP16(dst, src) \
    asm volatile("cp.async.cg.shared.global [%0], [%1], 16;" \
                 :: "r"((unsigned)(dst)), "l"(__cvta_generic_to_global(src)) : "memory")
#define CPC() asm volatile("cp.async.commit_group;" ::: "memory")
#define CPW0() asm volatile("cp.async.wait_group 0;" ::: "memory")
#define CPW1() asm volatile("cp.async.wait_group 1;" ::: "memory")

#define LDSM4(r0, r1, r2, r3, a) \
    asm volatile("ldmatrix.sync.aligned.m8n8.x4.shared.b16 {%0,%1,%2,%3}, [%4];" \
                 : "=r"(r0), "=r"(r1), "=r"(r2), "=r"(r3) : "r"((unsigned)(a)))

#define MMA(d, a0, a1, a2, a3, b0, b1) \
    asm volatile("mma.sync.aligned.m16n8k16.row.col.f32.f16.f16.f32 " \
                 "{%0,%1,%2,%3}, {%4,%5,%6,%7}, {%8,%9}, {%0,%1,%2,%3};" \
                 : "+f"((d)[0]), "+f"((d)[1]), "+f"((d)[2]), "+f"((d)[3]) \
                 : "r"(a0), "r"(a1), "r"(a2), "r"(a3), "r"(b0), "r"(b1))

// ---------------------------------------------------------------------------
// device globals (no allocation allowed)
// ---------------------------------------------------------------------------
__device__ float g_wl[D_];
__device__ float g_wr[D_];
__device__ __align__(16) float2 g_Elp[B_ * N_];   // (exp(hl), exp(0.2 hl))
__device__ __align__(16) float2 g_Erp[B_ * N_];   // (exp(hr), exp(0.2 hr))
__device__ __align__(16) __half g_Whf[D_ * D_];            // W fp16 row-major [o][k]
__device__ __align__(16) __half g_xh [B_ * N_ * D_];       // x fp16 row-major [m][k]
__device__ __align__(128) unsigned char g_ht[B_ * 32 * 32768]; // h^T fp16: [b][jt][d 256][j 64] swizzled

// ---------------- k_prep: block 0 -> wl/wr; blocks 1-16 -> W fp16 -----------
__global__ void k_prep(const float* __restrict__ W, const float* __restrict__ a)
{
    int t = threadIdx.x;                          // 1024 threads
    if (blockIdx.x == 0) {
        __shared__ float red[2][4][256];
        int d = t & 255, part = t >> 8;           // 4 o-partitions
        float sl = 0.f, sr = 0.f;
        int o0 = part * 64;
        #pragma unroll 8
        for (int o = o0; o < o0 + 64; ++o) {
            float w = W[o * D_ + d];
            sl = fmaf(a[o],      w, sl);
            sr = fmaf(a[D_ + o], w, sr);
        }
        red[0][part][d] = sl;
        red[1][part][d] = sr;
        __syncthreads();
        if (part == 0) {
            g_wl[d] = (red[0][0][d] + red[0][1][d]) + (red[0][2][d] + red[0][3][d]);
            g_wr[d] = (red[1][0][d] + red[1][1][d]) + (red[1][2][d] + red[1][3][d]);
        }
    } else {
        int i = (blockIdx.x - 1) * 1024 + t;      // one float4 each (16384 total)
        float4 v = ((const float4*)W)[i];
        __half2* o = (__half2*)g_Whf;
        o[i * 2]     = __floats2half2_rn(v.x, v.y);
        o[i * 2 + 1] = __floats2half2_rn(v.z, v.w);
    }
}

// ---------------- k_hlr: 2 rows/warp, hl/hr dots + exps + x->fp16 -----------
__global__ void k_hlr(const float* __restrict__ x)
{
    int w    = threadIdx.x >> 5;
    int lane = threadIdx.x & 31;
    int m0   = blockIdx.x * 16 + w * 2;           // rows m0, m0+1
    const float4* xr0 = (const float4*)(x + (size_t)m0 * D_);
    const float4* xr1 = (const float4*)(x + (size_t)(m0 + 1) * D_);
    const float4* wl4 = (const float4*)g_wl;
    const float4* wr4 = (const float4*)g_wr;

    float4 a0 = xr0[lane], a1 = xr0[lane + 32];   // 4 independent loads
    float4 b0 = xr1[lane], b1 = xr1[lane + 32];
    float4 l0 = wl4[lane], l1 = wl4[lane + 32];
    float4 r0 = wr4[lane], r1 = wr4[lane + 32];

    __half2* xo0 = (__half2*)(g_xh + (size_t)m0 * D_);
    __half2* xo1 = (__half2*)(g_xh + (size_t)(m0 + 1) * D_);
    xo0[lane * 2]            = __floats2half2_rn(a0.x, a0.y);
    xo0[lane * 2 + 1]        = __floats2half2_rn(a0.z, a0.w);
    xo0[(lane + 32) * 2]     = __floats2half2_rn(a1.x, a1.y);
    xo0[(lane + 32) * 2 + 1] = __floats2half2_rn(a1.z, a1.w);
    xo1[lane * 2]            = __floats2half2_rn(b0.x, b0.y);
    xo1[lane * 2 + 1]        = __floats2half2_rn(b0.z, b0.w);
    xo1[(lane + 32) * 2]     = __floats2half2_rn(b1.x, b1.y);
    xo1[(lane + 32) * 2 + 1] = __floats2half2_rn(b1.z, b1.w);

    float sl0 = a0.x * l0.x + a0.y * l0.y + a0.z * l0.z + a0.w * l0.w
              + a1.x * l1.x + a1.y * l1.y + a1.z * l1.z + a1.w * l1.w;
    float sr0 = a0.x * r0.x + a0.y * r0.y + a0.z * r0.z + a0.w * r0.w
              + a1.x * r1.x + a1.y * r1.y + a1.z * r1.z + a1.w * r1.w;
    float sl1 = b0.x * l0.x + b0.y * l0.y + b0.z * l0.z + b0.w * l0.w
              + b1.x * l1.x + b1.y * l1.y + b1.z * l1.z + b1.w * l1.w;
    float sr1 = b0.x * r0.x + b0.y * r0.y + b0.z * r0.z + b0.w * r0.w
              + b1.x * r1.x + b1.y * r1.y + b1.z * r1.z + b1.w * r1.w;

    #pragma unroll
    for (int off = 16; off > 0; off >>= 1) {
        sl0 += __shfl_xor_sync(0xFFFFFFFFu, sl0, off);
        sr0 += __shfl_xor_sync(0xFFFFFFFFu, sr0, off);
        sl1 += __shfl_xor_sync(0xFFFFFFFFu, sl1, off);
        sr1 += __shfl_xor_sync(0xFFFFFFFFu, sr1, off);
    }
    if (lane == 0) {
        g_Elp[m0]     = make_float2(expf(sl0), expf(0.2f * sl0));
        g_Erp[m0]     = make_float2(expf(sr0), expf(0.2f * sr0));
        g_Elp[m0 + 1] = make_float2(expf(sl1), expf(0.2f * sl1));
        g_Erp[m0 + 1] = make_float2(expf(sr1), expf(0.2f * sr1));
    }
}

// ---------------------------------------------------------------------------
// k_xh: h^T[d][j] = sum_k W[d][k] x[j][k]  (HMMA), smem-staged coalesced out
// CTA: 64 d x 256 j; warps m32 x n64; K loop 4 chunks of 64; 2 CTAs/SM
// ---------------------------------------------------------------------------
__global__ __launch_bounds__(256, 2) void k_xh()
{
    extern __shared__ char sm[];
    const int WS = 0, XS = 32768;
    unsigned sb = smem_u32(sm);
    int t = threadIdx.x, l = t & 31, w = t >> 5;
    int wm = w & 1, wn = w >> 1;
    int j0 = blockIdx.x * 256;
    int d0 = blockIdx.y * 64;

    #pragma unroll
    for (int q = 0; q < 8; ++q) {
        int idx = t + q * 256;
        int kc = idx >> 9, r = (idx >> 3) & 63, ch = idx & 7;
        CP16(sb + WS + kc * 8192 + SWZ(r * 128 + ch * 16),
             (const char*)g_Whf + (size_t)(d0 + r) * 512 + kc * 128 + ch * 16);
    }
    #pragma unroll
    for (int q = 0; q < 8; ++q) {
        int idx = t + q * 256, r = idx >> 3, ch = idx & 7;
        CP16(sb + XS + SWZ(r * 128 + ch * 16),
             (const char*)g_xh + (size_t)(j0 + r) * 512 + ch * 16);
    }
    CPC();

    float acc[8][2][4];
    #pragma unroll
    for (int i = 0; i < 8; ++i)
        #pragma unroll
        for (int m = 0; m < 2; ++m)
            #pragma unroll
            for (int c = 0; c < 4; ++c) acc[i][m][c] = 0.f;

    for (int kc = 0; kc < 4; ++kc) {
        if (kc < 3) {
            unsigned bbuf = sb + XS + ((kc + 1) & 1) * 32768;
            #pragma unroll
            for (int q = 0; q < 8; ++q) {
                int idx = t + q * 256, r = idx >> 3, ch = idx & 7;
                CP16(bbuf + SWZ(r * 128 + ch * 16),
                     (const char*)g_xh + (size_t)(j0 + r) * 512 + (kc + 1) * 128 + ch * 16);
            }
            CPC();
            CPW1();
        } else {
            CPW0();
        }
        __syncthreads();

        unsigned ab = sb + WS + kc * 8192;
        unsigned bb = sb + XS + (kc & 1) * 32768;
        #pragma unroll
        for (int ks = 0; ks < 4; ++ks) {
            unsigned a0[4], a1[4];
            LDSM4(a0[0], a0[1], a0[2], a0[3],
                  ab + SWZ((wm * 32      + (l & 15)) * 128 + ks * 32 + (l >> 4) * 16));
            LDSM4(a1[0], a1[1], a1[2], a1[3],
                  ab + SWZ((wm * 32 + 16 + (l & 15)) * 128 + ks * 32 + (l >> 4) * 16));
            #pragma unroll
            for (int nb2 = 0; nb2 < 4; ++nb2) {
                unsigned b0, b1, b2, b3;
                LDSM4(b0, b1, b2, b3,
                      bb + SWZ((wn * 64 + nb2 * 16 + (l & 15)) * 128 + ks * 32 + (l >> 4) * 16));
                MMA(acc[2*nb2][0],   a0[0], a0[1], a0[2], a0[3], b0, b2);
                MMA(acc[2*nb2][1],   a1[0], a1[1], a1[2], a1[3], b0, b2);
                MMA(acc[2*nb2+1][0], a0[0], a0[1], a0[2], a0[3], b1, b3);
                MMA(acc[2*nb2+1][1], a1[0], a1[1], a1[2], a1[3], b1, b3);
            }
        }
        __syncthreads();
    }

    // stage output (fp16, swizzled tile image) into smem, then coalesced copy
    #pragma unroll
    for (int mi = 0; mi < 2; ++mi) {
        int rd = wm * 32 + mi * 16 + (l >> 2);
        #pragma unroll
        for (int nb = 0; nb < 8; ++nb) {
            int jj = nb * 8 + 2 * (l & 3);
            __half2 v0 = __floats2half2_rn(acc[nb][mi][0], acc[nb][mi][1]);
            __half2 v1 = __floats2half2_rn(acc[nb][mi][2], acc[nb][mi][3]);
            *(__half2*)(sm + WS + wn * 8192 + SWZ( rd      * 128 + jj * 2)) = v0;
            *(__half2*)(sm + WS + wn * 8192 + SWZ((rd + 8) * 128 + jj * 2)) = v1;
        }
    }
    __syncthreads();

    int b   = j0 >> 11;
    int jt0 = (j0 & 2047) >> 6;
    #pragma unroll
    for (int q = 0; q < 8; ++q) {
        int c  = t + q * 256;                 // 2048 chunks x 16B
        int jt = c >> 9;
        int off = (c & 511) * 16;
        unsigned char* dst = g_ht + (size_t)(b * 32 + jt0 + jt) * 32768 + d0 * 128 + off;
        *(uint4*)dst = *(const uint4*)(sm + WS + c * 16);
    }
}

// ---------------------------------------------------------------------------
// k_aggr: fused masked-softmax aggregation (HMMA), 2 CTAs/SM for pipe overlap
// CTA 256 thr (8 warps): i-tile M=64, warp tile m32 x n64 (wm 0-1, wn 0-3)
// smem: H 2x32KB @0 | ADJ 2x16KB @65536 | P 8KB @98304 | ERT 2x512B @106496
//       | ELP 512B @107520 | RSUM 256B @108032   (total 108288 -> 2 CTAs/SM)
// iter t: barrier -> issue G(t+1) -> P(t) -> barrier -> MMA(t) -> wait0
//   (co-resident CTA fills the serialized phases' pipe bubbles)
// ---------------------------------------------------------------------------
__global__ __launch_bounds__(256, 2) void k_aggr(const int* __restrict__ adj,
                                                 float* __restrict__ out)
{
    extern __shared__ char sm[];
    const int HS = 0, AJ = 65536, PS = 98304, ERT = 106496;
    const int ELP = 107520, RSUM = 108032;
    unsigned sb = smem_u32(sm);
    int t = threadIdx.x, l = t & 31, w = t >> 5;
    int wm = w & 1, wn = w >> 1;
    int b = blockIdx.y, i0 = blockIdx.x * 64;
    float2* elp  = (float2*)(sm + ELP);
    float*  rsum = (float*)(sm + RSUM);

    const unsigned char* hsrc = g_ht + (size_t)b * 32 * 32768;
    const int*           adjb = adj + ((size_t)b * N_ + i0) * N_;
    const char*          ersrc = (const char*)(g_Erp + b * N_);

    // issue group nt: H(nt) 32KB + ADJ(nt) 16KB + Er(nt) 512B into bufs nt&1
    #define ISSUE_G(nt) do {                                                     \
        unsigned hdst = sb + HS + ((nt) & 1) * 32768;                            \
        unsigned adst = sb + AJ + ((nt) & 1) * 16384;                            \
        unsigned edst = sb + ERT + ((nt) & 1) * 512;                             \
        const unsigned char* hsr = hsrc + (size_t)(nt) * 32768;                  \
        const int*           asr = adjb + (nt) * 64;                             \
        _Pragma("unroll")                                                        \
        for (int q = 0; q < 8; ++q) {                                            \
            int idx = t + q * 256;                                               \
            CP16(hdst + idx * 16, hsr + idx * 16);                               \
        }                                                                        \
        _Pragma("unroll")                                                        \
        for (int q = 0; q < 4; ++q) {                                            \
            int idx = t + q * 256;                                               \
            CP16(adst + idx * 16, asr + ((size_t)(idx >> 4)) * N_ + (idx & 15) * 4); \
        }                                                                        \
        if (t < 32) CP16(edst + t * 16, ersrc + (nt) * 512 + t * 16);            \
        CPC();                                                                   \
    } while (0)

    // P(nt): p = adj ? max(El*Er, El2*Er2) : 0, 16 values/thread, single buffer
    #define P_PHASE(nt) do {                                                     \
        char* pb = sm + PS;                                                      \
        const int4*   aj4 = (const int4*)(sm + AJ + ((nt) & 1) * 16384);         \
        const float4* er4 = (const float4*)(sm + ERT + ((nt) & 1) * 512);        \
        _Pragma("unroll")                                                        \
        for (int rep = 0; rep < 4; ++rep) {                                      \
            int idx = t + rep * 256;                                             \
            int row = idx >> 4, c4 = idx & 15;                                   \
            int4 av = aj4[idx];                                                  \
            float2 el = elp[row];                                                \
            float4 ea = er4[c4 * 2];                                             \
            float4 eb = er4[c4 * 2 + 1];                                         \
            float p0 = fmaxf(el.x * ea.x, el.y * ea.y);                          \
            float p1 = fmaxf(el.x * ea.z, el.y * ea.w);                          \
            float p2 = fmaxf(el.x * eb.x, el.y * eb.y);                          \
            float p3 = fmaxf(el.x * eb.z, el.y * eb.w);                          \
            p0 = av.x ? p0 : 0.f;  p1 = av.y ? p1 : 0.f;                         \
            p2 = av.z ? p2 : 0.f;  p3 = av.w ? p3 : 0.f;                         \
            __half2 h01 = __floats2half2_rn(p0, p1);                             \
            __half2 h23 = __floats2half2_rn(p2, p3);                             \
            uint2 pk;                                                            \
            pk.x = *(unsigned*)&h01;                                             \
            pk.y = *(unsigned*)&h23;                                             \
            *(uint2*)(pb + SWZ(row * 128 + c4 * 8)) = pk;                        \
        }                                                                        \
    } while (0)

    // prologue: ELP + G(0)
    if (t < 32) CP16(sb + ELP + t * 16, (const char*)(g_Elp + b * N_ + i0) + t * 16);
    ISSUE_G(0);
    CPW0();

    float acc[8][2][4];
    #pragma unroll
    for (int i = 0; i < 8; ++i)
        #pragma unroll
        for (int m = 0; m < 2; ++m)
            #pragma unroll
            for (int c = 0; c < 4; ++c) acc[i][m][c] = 0.f;
    float sacc[2][4] = {{0.f,0.f,0.f,0.f},{0.f,0.f,0.f,0.f}};
    const unsigned ONESH = 0x3C003C00u;

    for (int tile = 0; tile < 32; ++tile) {
        __syncthreads();            // G(tile) CTA-visible; MMA(tile-1) done
        if (tile < 31) ISSUE_G(tile + 1);
        P_PHASE(tile);
        __syncthreads();            // P visible to all warps

        unsigned pbase = sb + PS;
        unsigned hbase = sb + HS + (tile & 1) * 32768;
        #pragma unroll
        for (int ks = 0; ks < 4; ++ks) {
            unsigned a0[4], a1[4];
            LDSM4(a0[0], a0[1], a0[2], a0[3],
                  pbase + SWZ((wm * 32      + (l & 15)) * 128 + ks * 32 + (l >> 4) * 16));
            LDSM4(a1[0], a1[1], a1[2], a1[3],
                  pbase + SWZ((wm * 32 + 16 + (l & 15)) * 128 + ks * 32 + (l >> 4) * 16));
            if (wn == 0) {
                MMA(sacc[0], a0[0], a0[1], a0[2], a0[3], ONESH, ONESH);
                MMA(sacc[1], a1[0], a1[1], a1[2], a1[3], ONESH, ONESH);
            }
            #pragma unroll
            for (int nb2 = 0; nb2 < 4; ++nb2) {
                unsigned b0, b1, b2, b3;
                LDSM4(b0, b1, b2, b3,
                      hbase + SWZ((wn * 64 + nb2 * 16 + (l & 15)) * 128 + ks * 32 + (l >> 4) * 16));
                MMA(acc[2*nb2][0],   a0[0], a0[1], a0[2], a0[3], b0, b2);
                MMA(acc[2*nb2][1],   a1[0], a1[1], a1[2], a1[3], b0, b2);
                MMA(acc[2*nb2+1][0], a0[0], a0[1], a0[2], a0[3], b1, b3);
                MMA(acc[2*nb2+1][1], a1[0], a1[1], a1[2], a1[3], b1, b3);
            }
        }
        if (tile < 31) CPW0();      // G(tile+1) landed (per-thread)
    }

    __syncthreads();
    if (wn == 0 && (l & 3) == 0) {
        int r = wm * 32 + (l >> 2);
        rsum[r]      = sacc[0][0];
        rsum[r + 8]  = sacc[0][2];
        rsum[r + 16] = sacc[1][0];
        rsum[r + 24] = sacc[1][2];
    }
    __syncthreads();

    #pragma unroll
    for (int mi = 0; mi < 2; ++mi) {
        int r0 = wm * 32 + mi * 16 + (l >> 2);
        float s0 = rsum[r0], s1 = rsum[r0 + 8];
        float inv0 = (s0 > 0.f) ? 1.f / s0 : 0.f;
        float inv1 = (s1 > 0.f) ? 1.f / s1 : 0.f;
        float* o0 = out + ((size_t)b * N_ + i0 + r0) * D_;
        float* o1 = o0 + 8 * D_;
        #pragma unroll
        for (int nb = 0; nb < 8; ++nb) {
            int c = wn * 64 + nb * 8 + 2 * (l & 3);
            *(float2*)(o0 + c) = make_float2(acc[nb][mi][0] * inv0,
                                             acc[nb][mi][1] * inv0);
            *(float2*)(o1 + c) = make_float2(acc[nb][mi][2] * inv1,
                                             acc[nb][mi][3] * inv1);
        }
    }
}

// ---------------------------------------------------------------------------
extern "C" void kernel_launch(void* const* d_in, const int* in_sizes, int n_in,
                              void* d_out, int out_size)
{
    const float* x   = (const float*)d_in[0];   // (8,2048,256) f32
    const int*   adj = (const int*)  d_in[1];   // (8,2048,2048) i32
    const float* W   = (const float*)d_in[2];   // (256,256) f32
    const float* a   = (const float*)d_in[3];   // (1,512) f32
    float*       out = (float*)d_out;           // (8,2048,256) f32

    cudaFuncSetAttribute(k_xh,   cudaFuncAttributeMaxDynamicSharedMemorySize, 98304);
    cudaFuncSetAttribute(k_aggr, cudaFuncAttributeMaxDynamicSharedMemorySize, 108288);

    k_prep <<<17, 1024>>>(W, a);
    k_hlr  <<<(B_ * N_) / 16, 256>>>(x);
    k_xh   <<<dim3((B_ * N_) / 256, D_ / 64), 256, 98304>>>();
    k_aggr <<<dim3(N_ / 64, B_), 256, 108288>>>(adj, out);
}

// round 16
// speedup vs baseline: 1.1488x; 1.0195x over previous
#include <cuda_runtime.h>
#include <cuda_fp16.h>
#include <math.h>
#include <stdint.h>

#define B_ 8
#define N_ 2048
#define D_ 256

// ---------------------------------------------------------------------------
// helpers (baseline PTX only: cp.async / ldmatrix / mma.sync — compute_100 OK)
// ---------------------------------------------------------------------------
__device__ __forceinline__ unsigned smem_u32(const void* p) {
    unsigned a;
    asm("{ .reg .u64 t; cvta.to.shared.u64 t, %1; cvt.u32.u64 %0, t; }"
        : "=r"(a) : "l"(p));
    return a;
}
__device__ __forceinline__ int SWZ(int x) { return x ^ ((x >> 3) & 0x70); }

#define CP16(dst, src) \
    asm volatile("cp.async.cg.shared.global [%0], [%1], 16;" \
                 :: "r"((unsigned)(dst)), "l"(__cvta_generic_to_global(src)) : "memory")
#define CPC() asm volatile("cp.async.commit_group;" ::: "memory")
#define CPW0() asm volatile("cp.async.wait_group 0;" ::: "memory")
#define CPW1() asm volatile("cp.async.wait_group 1;" ::: "memory")

#define LDSM4(r0, r1, r2, r3, a) \
    asm volatile("ldmatrix.sync.aligned.m8n8.x4.shared.b16 {%0,%1,%2,%3}, [%4];" \
                 : "=r"(r0), "=r"(r1), "=r"(r2), "=r"(r3) : "r"((unsigned)(a)))

#define MMA(d, a0, a1, a2, a3, b0, b1) \
    asm volatile("mma.sync.aligned.m16n8k16.row.col.f32.f16.f16.f32 " \
                 "{%0,%1,%2,%3}, {%4,%5,%6,%7}, {%8,%9}, {%0,%1,%2,%3};" \
                 : "+f"((d)[0]), "+f"((d)[1]), "+f"((d)[2]), "+f"((d)[3]) \
                 : "r"(a0), "r"(a1), "r"(a2), "r"(a3), "r"(b0), "r"(b1))

// ---------------------------------------------------------------------------
// device globals (no allocation allowed)
// ---------------------------------------------------------------------------
__device__ float g_wl[D_];
__device__ float g_wr[D_];
__device__ __align__(16) float2 g_Elp[B_ * N_];   // (exp(hl), exp(0.2 hl))
__device__ __align__(16) float2 g_Erp[B_ * N_];   // (exp(hr), exp(0.2 hr))
__device__ __align__(16) __half g_Whf[D_ * D_];            // W fp16 row-major [o][k]
__device__ __align__(16) __half g_xh [B_ * N_ * D_];       // x fp16 row-major [m][k]
__device__ __align__(128) unsigned char g_ht[B_ * 32 * 32768]; // h^T fp16: [b][jt][d 256][j 64] swizzled

// ---------------- k_prep: block 0 -> wl/wr; blocks 1-16 -> W fp16 -----------
__global__ void k_prep(const float* __restrict__ W, const float* __restrict__ a)
{
    int t = threadIdx.x;                          // 1024 threads
    if (blockIdx.x == 0) {
        __shared__ float red[2][4][256];
        int d = t & 255, part = t >> 8;           // 4 o-partitions
        float sl = 0.f, sr = 0.f;
        int o0 = part * 64;
        #pragma unroll 8
        for (int o = o0; o < o0 + 64; ++o) {
            float w = W[o * D_ + d];
            sl = fmaf(a[o],      w, sl);
            sr = fmaf(a[D_ + o], w, sr);
        }
        red[0][part][d] = sl;
        red[1][part][d] = sr;
        __syncthreads();
        if (part == 0) {
            g_wl[d] = (red[0][0][d] + red[0][1][d]) + (red[0][2][d] + red[0][3][d]);
            g_wr[d] = (red[1][0][d] + red[1][1][d]) + (red[1][2][d] + red[1][3][d]);
        }
    } else {
        int i = (blockIdx.x - 1) * 1024 + t;      // one float4 each (16384 total)
        float4 v = ((const float4*)W)[i];
        __half2* o = (__half2*)g_Whf;
        o[i * 2]     = __floats2half2_rn(v.x, v.y);
        o[i * 2 + 1] = __floats2half2_rn(v.z, v.w);
    }
}

// ---------------- k_hlr: 4 rows/warp, hl/hr dots + exps + x->fp16 -----------
__global__ void k_hlr(const float* __restrict__ x)
{
    int w    = threadIdx.x >> 5;
    int lane = threadIdx.x & 31;
    int m0   = blockIdx.x * 32 + w * 4;           // rows m0..m0+3
    const float4* wl4 = (const float4*)g_wl;
    const float4* wr4 = (const float4*)g_wr;

    float4 xv[4][2];
    #pragma unroll
    for (int r = 0; r < 4; ++r) {
        const float4* xr = (const float4*)(x + (size_t)(m0 + r) * D_);
        xv[r][0] = xr[lane];
        xv[r][1] = xr[lane + 32];
    }
    float4 l0 = wl4[lane], l1 = wl4[lane + 32];
    float4 r0 = wr4[lane], r1 = wr4[lane + 32];

    float sl[4], sr[4];
    #pragma unroll
    for (int r = 0; r < 4; ++r) {
        __half2* xo = (__half2*)(g_xh + (size_t)(m0 + r) * D_);
        float4 v0 = xv[r][0], v1 = xv[r][1];
        xo[lane * 2]            = __floats2half2_rn(v0.x, v0.y);
        xo[lane * 2 + 1]        = __floats2half2_rn(v0.z, v0.w);
        xo[(lane + 32) * 2]     = __floats2half2_rn(v1.x, v1.y);
        xo[(lane + 32) * 2 + 1] = __floats2half2_rn(v1.z, v1.w);
        sl[r] = v0.x * l0.x + v0.y * l0.y + v0.z * l0.z + v0.w * l0.w
              + v1.x * l1.x + v1.y * l1.y + v1.z * l1.z + v1.w * l1.w;
        sr[r] = v0.x * r0.x + v0.y * r0.y + v0.z * r0.z + v0.w * r0.w
              + v1.x * r1.x + v1.y * r1.y + v1.z * r1.z + v1.w * r1.w;
    }
    #pragma unroll
    for (int off = 16; off > 0; off >>= 1) {
        #pragma unroll
        for (int r = 0; r < 4; ++r) {
            sl[r] += __shfl_xor_sync(0xFFFFFFFFu, sl[r], off);
            sr[r] += __shfl_xor_sync(0xFFFFFFFFu, sr[r], off);
        }
    }
    if (lane == 0) {
        #pragma unroll
        for (int r = 0; r < 4; ++r) {
            g_Elp[m0 + r] = make_float2(expf(sl[r]), expf(0.2f * sl[r]));
            g_Erp[m0 + r] = make_float2(expf(sr[r]), expf(0.2f * sr[r]));
        }
    }
}

// ---------------------------------------------------------------------------
// k_xh: h^T[d][j] = sum_k W[d][k] x[j][k]  (HMMA), smem-staged coalesced out
// CTA: 64 d x 256 j; warps m32 x n64; K loop 4 chunks of 64; 2 CTAs/SM
// ---------------------------------------------------------------------------
__global__ __launch_bounds__(256, 2) void k_xh()
{
    extern __shared__ char sm[];
    const int WS = 0, XS = 32768;
    unsigned sb = smem_u32(sm);
    int t = threadIdx.x, l = t & 31, w = t >> 5;
    int wm = w & 1, wn = w >> 1;
    int j0 = blockIdx.x * 256;
    int d0 = blockIdx.y * 64;

    #pragma unroll
    for (int q = 0; q < 8; ++q) {
        int idx = t + q * 256;
        int kc = idx >> 9, r = (idx >> 3) & 63, ch = idx & 7;
        CP16(sb + WS + kc * 8192 + SWZ(r * 128 + ch * 16),
             (const char*)g_Whf + (size_t)(d0 + r) * 512 + kc * 128 + ch * 16);
    }
    #pragma unroll
    for (int q = 0; q < 8; ++q) {
        int idx = t + q * 256, r = idx >> 3, ch = idx & 7;
        CP16(sb + XS + SWZ(r * 128 + ch * 16),
             (const char*)g_xh + (size_t)(j0 + r) * 512 + ch * 16);
    }
    CPC();

    float acc[8][2][4];
    #pragma unroll
    for (int i = 0; i < 8; ++i)
        #pragma unroll
        for (int m = 0; m < 2; ++m)
            #pragma unroll
            for (int c = 0; c < 4; ++c) acc[i][m][c] = 0.f;

    for (int kc = 0; kc < 4; ++kc) {
        if (kc < 3) {
            unsigned bbuf = sb + XS + ((kc + 1) & 1) * 32768;
            #pragma unroll
            for (int q = 0; q < 8; ++q) {
                int idx = t + q * 256, r = idx >> 3, ch = idx & 7;
                CP16(bbuf + SWZ(r * 128 + ch * 16),
                     (const char*)g_xh + (size_t)(j0 + r) * 512 + (kc + 1) * 128 + ch * 16);
            }
            CPC();
            CPW1();
        } else {
            CPW0();
        }
        __syncthreads();

        unsigned ab = sb + WS + kc * 8192;
        unsigned bb = sb + XS + (kc & 1) * 32768;
        #pragma unroll
        for (int ks = 0; ks < 4; ++ks) {
            unsigned a0[4], a1[4];
            LDSM4(a0[0], a0[1], a0[2], a0[3],
                  ab + SWZ((wm * 32      + (l & 15)) * 128 + ks * 32 + (l >> 4) * 16));
            LDSM4(a1[0], a1[1], a1[2], a1[3],
                  ab + SWZ((wm * 32 + 16 + (l & 15)) * 128 + ks * 32 + (l >> 4) * 16));
            #pragma unroll
            for (int nb2 = 0; nb2 < 4; ++nb2) {
                unsigned b0, b1, b2, b3;
                LDSM4(b0, b1, b2, b3,
                      bb + SWZ((wn * 64 + nb2 * 16 + (l & 15)) * 128 + ks * 32 + (l >> 4) * 16));
                MMA(acc[2*nb2][0],   a0[0], a0[1], a0[2], a0[3], b0, b2);
                MMA(acc[2*nb2][1],   a1[0], a1[1], a1[2], a1[3], b0, b2);
                MMA(acc[2*nb2+1][0], a0[0], a0[1], a0[2], a0[3], b1, b3);
                MMA(acc[2*nb2+1][1], a1[0], a1[1], a1[2], a1[3], b1, b3);
            }
        }
        __syncthreads();
    }

    // stage output (fp16, swizzled tile image) into smem, then coalesced copy
    #pragma unroll
    for (int mi = 0; mi < 2; ++mi) {
        int rd = wm * 32 + mi * 16 + (l >> 2);
        #pragma unroll
        for (int nb = 0; nb < 8; ++nb) {
            int jj = nb * 8 + 2 * (l & 3);
            __half2 v0 = __floats2half2_rn(acc[nb][mi][0], acc[nb][mi][1]);
            __half2 v1 = __floats2half2_rn(acc[nb][mi][2], acc[nb][mi][3]);
            *(__half2*)(sm + WS + wn * 8192 + SWZ( rd      * 128 + jj * 2)) = v0;
            *(__half2*)(sm + WS + wn * 8192 + SWZ((rd + 8) * 128 + jj * 2)) = v1;
        }
    }
    __syncthreads();

    int b   = j0 >> 11;
    int jt0 = (j0 & 2047) >> 6;
    #pragma unroll
    for (int q = 0; q < 8; ++q) {
        int c  = t + q * 256;                 // 2048 chunks x 16B
        int jt = c >> 9;
        int off = (c & 511) * 16;
        unsigned char* dst = g_ht + (size_t)(b * 32 + jt0 + jt) * 32768 + d0 * 128 + off;
        *(uint4*)dst = *(const uint4*)(sm + WS + c * 16);
    }
}

// ---------------------------------------------------------------------------
// k_aggr: fused masked-softmax aggregation (HMMA), 2 CTAs/SM
// CTA 256 thr (8 warps): i-tile M=64, warp tile m32 x n64 (wm 0-1, wn 0-3)
// R15: Er in registers (LDG prefetch, rep-invariant per thread), row sums as
//      fp32 accumulation in P-phase (ones-MMA removed)
// smem: H 2x32KB @0 | ADJ 2x16KB @65536 | P 8KB @98304 | ELP 512B @106496
//       | RSUM 256B @107008   (total 107264 -> 2 CTAs/SM)
// iter t: barrier -> issue G(t+1) -> P(t) -> prefetch Er(t+1) -> barrier ->
//         MMA(t) -> wait0
// ---------------------------------------------------------------------------
__global__ __launch_bounds__(256, 2) void k_aggr(const int* __restrict__ adj,
                                                 float* __restrict__ out)
{
    extern __shared__ char sm[];
    const int HS = 0, AJ = 65536, PS = 98304, ELP = 106496, RSUM = 107008;
    unsigned sb = smem_u32(sm);
    int t = threadIdx.x, l = t & 31, w = t >> 5;
    int wm = w & 1, wn = w >> 1;
    int b = blockIdx.y, i0 = blockIdx.x * 64;
    float2* elp  = (float2*)(sm + ELP);
    float*  rsum = (float*)(sm + RSUM);

    const unsigned char* hsrc = g_ht + (size_t)b * 32 * 32768;
    const int*           adjb = adj + ((size_t)b * N_ + i0) * N_;
    const float4*        erg  = (const float4*)g_Erp + (size_t)b * (N_ / 2);
    int c4 = t & 15;

    // issue group nt: H(nt) 32KB + ADJ(nt) 16KB into bufs nt&1
    #define ISSUE_G(nt) do {                                                     \
        unsigned hdst = sb + HS + ((nt) & 1) * 32768;                            \
        unsigned adst = sb + AJ + ((nt) & 1) * 16384;                            \
        const unsigned char* hsr = hsrc + (size_t)(nt) * 32768;                  \
        const int*           asr = adjb + (nt) * 64;                             \
        _Pragma("unroll")                                                        \
        for (int q = 0; q < 8; ++q) {                                            \
            int idx = t + q * 256;                                               \
            CP16(hdst + idx * 16, hsr + idx * 16);                               \
        }                                                                        \
        _Pragma("unroll")                                                        \
        for (int q = 0; q < 4; ++q) {                                            \
            int idx = t + q * 256;                                               \
            CP16(adst + idx * 16, asr + ((size_t)(idx >> 4)) * N_ + (idx & 15) * 4); \
        }                                                                        \
        CPC();                                                                   \
    } while (0)

    // P(nt): p = adj ? max(El*Er, El2*Er2) : 0; Er in regs ea/eb; rsum in rs[]
    #define P_PHASE(nt, ea, eb) do {                                             \
        char* pb = sm + PS;                                                      \
        const int4* aj4 = (const int4*)(sm + AJ + ((nt) & 1) * 16384);           \
        _Pragma("unroll")                                                        \
        for (int rep = 0; rep < 4; ++rep) {                                      \
            int idx = t + rep * 256;                                             \
            int row = idx >> 4;                                                  \
            int4 av = aj4[idx];                                                  \
            float2 el = elp[row];                                                \
            float p0 = fmaxf(el.x * (ea).x, el.y * (ea).y);                      \
            float p1 = fmaxf(el.x * (ea).z, el.y * (ea).w);                      \
            float p2 = fmaxf(el.x * (eb).x, el.y * (eb).y);                      \
            float p3 = fmaxf(el.x * (eb).z, el.y * (eb).w);                      \
            p0 = av.x ? p0 : 0.f;  p1 = av.y ? p1 : 0.f;                         \
            p2 = av.z ? p2 : 0.f;  p3 = av.w ? p3 : 0.f;                         \
            rs[rep] += (p0 + p1) + (p2 + p3);                                    \
            __half2 h01 = __floats2half2_rn(p0, p1);                             \
            __half2 h23 = __floats2half2_rn(p2, p3);                             \
            uint2 pk;                                                            \
            pk.x = *(unsigned*)&h01;                                             \
            pk.y = *(unsigned*)&h23;                                             \
            *(uint2*)(pb + SWZ(row * 128 + c4 * 8)) = pk;                        \
        }                                                                        \
    } while (0)

    // prologue: ELP + G(0); Er(0) straight to registers
    if (t < 32) CP16(sb + ELP + t * 16, (const char*)(g_Elp + b * N_ + i0) + t * 16);
    ISSUE_G(0);
    float4 ecur0 = erg[c4 * 2];
    float4 ecur1 = erg[c4 * 2 + 1];
    CPW0();

    float rs[4] = {0.f, 0.f, 0.f, 0.f};
    float acc[8][2][4];
    #pragma unroll
    for (int i = 0; i < 8; ++i)
        #pragma unroll
        for (int m = 0; m < 2; ++m)
            #pragma unroll
            for (int c = 0; c < 4; ++c) acc[i][m][c] = 0.f;

    for (int tile = 0; tile < 32; ++tile) {
        __syncthreads();            // G(tile) CTA-visible; MMA(tile-1) done
        if (tile < 31) ISSUE_G(tile + 1);
        P_PHASE(tile, ecur0, ecur1);
        float4 enxt0, enxt1;
        if (tile < 31) {            // prefetch Er(tile+1); lands under MMA
            enxt0 = erg[(tile + 1) * 32 + c4 * 2];
            enxt1 = erg[(tile + 1) * 32 + c4 * 2 + 1];
        }
        __syncthreads();            // P visible to all warps

        unsigned pbase = sb + PS;
        unsigned hbase = sb + HS + (tile & 1) * 32768;
        #pragma unroll
        for (int ks = 0; ks < 4; ++ks) {
            unsigned a0[4], a1[4];
            LDSM4(a0[0], a0[1], a0[2], a0[3],
                  pbase + SWZ((wm * 32      + (l & 15)) * 128 + ks * 32 + (l >> 4) * 16));
            LDSM4(a1[0], a1[1], a1[2], a1[3],
                  pbase + SWZ((wm * 32 + 16 + (l & 15)) * 128 + ks * 32 + (l >> 4) * 16));
            #pragma unroll
            for (int nb2 = 0; nb2 < 4; ++nb2) {
                unsigned b0, b1, b2, b3;
                LDSM4(b0, b1, b2, b3,
                      hbase + SWZ((wn * 64 + nb2 * 16 + (l & 15)) * 128 + ks * 32 + (l >> 4) * 16));
                MMA(acc[2*nb2][0],   a0[0], a0[1], a0[2], a0[3], b0, b2);
                MMA(acc[2*nb2][1],   a1[0], a1[1], a1[2], a1[3], b0, b2);
                MMA(acc[2*nb2+1][0], a0[0], a0[1], a0[2], a0[3], b1, b3);
                MMA(acc[2*nb2+1][1], a1[0], a1[1], a1[2], a1[3], b1, b3);
            }
        }
        if (tile < 31) {
            CPW0();                 // G(tile+1) landed (per-thread)
            ecur0 = enxt0;
            ecur1 = enxt1;
        }
    }

    // reduce row sums: 16 threads (same t>>4) share each row; rows tile-invariant
    #pragma unroll
    for (int off = 8; off > 0; off >>= 1)
        #pragma unroll
        for (int rep = 0; rep < 4; ++rep)
            rs[rep] += __shfl_xor_sync(0xFFFFFFFFu, rs[rep], off);
    __syncthreads();
    if ((t & 15) == 0) {
        #pragma unroll
        for (int rep = 0; rep < 4; ++rep)
            rsum[(t >> 4) + rep * 16] = rs[rep];
    }
    __syncthreads();

    #pragma unroll
    for (int mi = 0; mi < 2; ++mi) {
        int r0 = wm * 32 + mi * 16 + (l >> 2);
        float s0 = rsum[r0], s1 = rsum[r0 + 8];
        float inv0 = (s0 > 0.f) ? 1.f / s0 : 0.f;
        float inv1 = (s1 > 0.f) ? 1.f / s1 : 0.f;
        float* o0 = out + ((size_t)b * N_ + i0 + r0) * D_;
        float* o1 = o0 + 8 * D_;
        #pragma unroll
        for (int nb = 0; nb < 8; ++nb) {
            int c = wn * 64 + nb * 8 + 2 * (l & 3);
            *(float2*)(o0 + c) = make_float2(acc[nb][mi][0] * inv0,
                                             acc[nb][mi][1] * inv0);
            *(float2*)(o1 + c) = make_float2(acc[nb][mi][2] * inv1,
                                             acc[nb][mi][3] * inv1);
        }
    }
}

// ---------------------------------------------------------------------------
extern "C" void kernel_launch(void* const* d_in, const int* in_sizes, int n_in,
                              void* d_out, int out_size)
{
    const float* x   = (const float*)d_in[0];   // (8,2048,256) f32
    const int*   adj = (const int*)  d_in[1];   // (8,2048,2048) i32
    const float* W   = (const float*)d_in[2];   // (256,256) f32
    const float* a   = (const float*)d_in[3];   // (1,512) f32
    float*       out = (float*)d_out;           // (8,2048,256) f32

    cudaFuncSetAttribute(k_xh,   cudaFuncAttributeMaxDynamicSharedMemorySize, 98304);
    cudaFuncSetAttribute(k_aggr, cudaFuncAttributeMaxDynamicSharedMemorySize, 107264);

    k_prep <<<17, 1024>>>(W, a);
    k_hlr  <<<(B_ * N_) / 32, 256>>>(x);
    k_xh   <<<dim3((B_ * N_) / 256, D_ / 64), 256, 98304>>>();
    k_aggr <<<dim3(N_ / 64, B_), 256, 107264>>>(adj, out);
}